// round 14
// baseline (speedup 1.0000x reference)
#include <cuda_runtime.h>
#include <cuda_bf16.h>
#include <math.h>

#define F 128
#define NMAX 50000
#define EMAX 800000
#define CAP 64      // bucket capacity per destination row (P(deg>=64) ~ 1e-13)

typedef unsigned int       u32;
typedef unsigned short     u16;
typedef unsigned long long u64;

// static scratch (no allocations allowed; zero-initialized at load)
__device__ u16    g_Shi[(size_t)NMAX * F];         // bf16 hi of S
__device__ u16    g_Slo[(size_t)NMAX * F];         // bf16 residual of S
__device__ u16    g_WTa[F * F];                    // bf16 hi of W'^T  [n][k]
__device__ u16    g_WTb[F * F];                    // bf16 residual    [n][k]
__device__ float2 g_slots[(size_t)NMAX * CAP];     // (src_bits, w) buckets
__device__ int    g_cnt[NMAX];                     // reset by epilogue for next call
__device__ float4 g_over[EMAX];                    // overflow edges
__device__ int    g_overcnt;

// ---------------------------------------------------------------------------
// Kernel 1: bucket fill (1 edge/thread — proven throughput-bound config)
// + fused W'^T hi/lo build in the first 64 blocks (no extra launch).
// ---------------------------------------------------------------------------
__global__ void fill_kernel(const float* __restrict__ edge_w,
                            const int* __restrict__ edge_src,
                            const int* __restrict__ edge_dst,
                            int E,
                            const float* __restrict__ weight,
                            const float* __restrict__ lamda_p,
                            const int* __restrict__ l_p) {
    int e = blockIdx.x * blockDim.x + threadIdx.x;
    if (e < E) {
        int d = edge_dst[e];
        int s = edge_src[e];
        float w = edge_w[e];
        int pos = atomicAdd(&g_cnt[d], 1);
        if (pos < CAP) {
            g_slots[(size_t)d * CAP + pos] = make_float2(__int_as_float(s), w);
        } else {
            int o = atomicAdd(&g_overcnt, 1);
            if (o < EMAX)
                g_over[o] = make_float4(__int_as_float(s), __int_as_float(d), w, 0.f);
        }
    }
    // WT build: blocks 0..63 cover all 16384 elements
    if (blockIdx.x < 64) {
        int i = blockIdx.x * 256 + threadIdx.x;     // 0..16383
        int k = i >> 7;
        int n = i & 127;
        float theta = logf(lamda_p[0] / (float)l_p[0] + 1.0f);
        float v = theta * weight[i];                // weight[k][n]
        if (k == n) v += 1.0f - theta;
        __nv_bfloat16 h = __float2bfloat16(v);
        float res = v - __bfloat162float(h);
        __nv_bfloat16 l = __float2bfloat16(res);
        g_WTa[n * F + k] = *(u16*)&h;               // WT[n][k] = W'[k][n]
        g_WTb[n * F + k] = *(u16*)&l;
    }
}

// ---------------------------------------------------------------------------
// Kernel 2: gather + S fuse + bf16 hi/lo split. One warp per row (R12-proven).
// ---------------------------------------------------------------------------
__global__ void gather_kernel(const float* __restrict__ x,
                              const float* __restrict__ h0,
                              const float* __restrict__ alpha_p,
                              int Nn) {
    int gtid = blockIdx.x * blockDim.x + threadIdx.x;
    int row = gtid >> 5;
    int lane = gtid & 31;
    if (row >= Nn) return;

    float alpha = alpha_p[0];
    float oma = 1.0f - alpha;

    int cnt_raw = g_cnt[row];
    int cnt = min(cnt_raw, CAP);

    float4 acc = make_float4(0.f, 0.f, 0.f, 0.f);
    const float2* slotp = g_slots + (size_t)row * CAP;

    for (int base = 0; base < cnt; base += 32) {
        int m = min(32, cnt - base);
        float2 myslot = (lane < m) ? slotp[base + lane] : make_float2(0.f, 0.f);
        int ms = __float_as_int(myslot.x);
        #pragma unroll 4
        for (int e = 0; e < m; e++) {
            int   s  = __shfl_sync(0xffffffffu, ms, e);
            float wt = __shfl_sync(0xffffffffu, myslot.y, e);
            float4 v = ((const float4*)(x + (size_t)s * F))[lane];
            acc.x += wt * v.x;
            acc.y += wt * v.y;
            acc.z += wt * v.z;
            acc.w += wt * v.w;
        }
    }

    if (cnt_raw > CAP) {                       // statistically never
        int oc = g_overcnt;
        if (oc > EMAX) oc = EMAX;
        for (int o = 0; o < oc; o++) {
            float4 ov = g_over[o];
            if (__float_as_int(ov.y) == row) {
                int s = __float_as_int(ov.x);
                float wt = ov.z;
                float4 v = ((const float4*)(x + (size_t)s * F))[lane];
                acc.x += wt * v.x;
                acc.y += wt * v.y;
                acc.z += wt * v.z;
                acc.w += wt * v.w;
            }
        }
    }

    float4 hv = ((const float4*)(h0 + (size_t)row * F))[lane];
    float Sx = oma * acc.x + alpha * hv.x;
    float Sy = oma * acc.y + alpha * hv.y;
    float Sz = oma * acc.z + alpha * hv.z;
    float Sw = oma * acc.w + alpha * hv.w;

    __nv_bfloat162 h01 = __floats2bfloat162_rn(Sx, Sy);
    __nv_bfloat162 h23 = __floats2bfloat162_rn(Sz, Sw);
    __nv_bfloat162 l01 = __floats2bfloat162_rn(
        Sx - __bfloat162float(h01.x), Sy - __bfloat162float(h01.y));
    __nv_bfloat162 l23 = __floats2bfloat162_rn(
        Sz - __bfloat162float(h23.x), Sw - __bfloat162float(h23.y));
    u64 hvv = (u64)(*(u32*)&h01) | ((u64)(*(u32*)&h23) << 32);
    u64 lvv = (u64)(*(u32*)&l01) | ((u64)(*(u32*)&l23) << 32);
    *(u64*)&g_Shi[(size_t)row * F + 4 * lane] = hvv;
    *(u64*)&g_Slo[(size_t)row * F + 4 * lane] = lvv;
}

// ---------------------------------------------------------------------------
// Kernel 3: HMMA epilogue, small-smem / high-occupancy version.
//   out = S @ W' + x; D = Sa@Wa + Sb@Wa + Sa@Wb (fp32 accum).
// R14 vs R12: WT lives in GLOBAL (built by fill; stays L1-resident, 64KB),
// smem holds ONLY the 16-row S staging (8.7 KB) -> __launch_bounds__(256,3)
// gives 3 blocks/SM = 24 warps (was 16, smem-capped). B fragments are
// LDG.32 from g_WTa/g_WTb inside the loop (L1 hits).
// ---------------------------------------------------------------------------
#define SPAD 136                        // u16 row stride (272 bytes)
#define OFF_SA  0
#define OFF_SB  (16 * SPAD * 2)
#define SMEM_EPI (2 * 16 * SPAD * 2)    // 8704 bytes

#define MMA_BF16(c, a0, a1, a2, a3, b0, b1) \
    asm volatile("mma.sync.aligned.m16n8k16.row.col.f32.bf16.bf16.f32 " \
        "{%0,%1,%2,%3}, {%4,%5,%6,%7}, {%8,%9}, {%0,%1,%2,%3};" \
        : "+f"((c)[0]), "+f"((c)[1]), "+f"((c)[2]), "+f"((c)[3]) \
        : "r"(a0), "r"(a1), "r"(a2), "r"(a3), "r"(b0), "r"(b1))

#define LDMATRIX_X4(r0, r1, r2, r3, addr) \
    asm volatile("ldmatrix.sync.aligned.m8n8.x4.shared.b16 {%0,%1,%2,%3}, [%4];" \
        : "=r"(r0), "=r"(r1), "=r"(r2), "=r"(r3) : "r"(addr))

__device__ __forceinline__ u32 smem_u32(const void* p) {
    u32 a;
    asm("{ .reg .u64 t; cvta.to.shared.u64 t, %1; cvt.u32.u64 %0, t; }"
        : "=r"(a) : "l"(p));
    return a;
}

__global__ void __launch_bounds__(256, 3)
mma_epilogue_kernel(const float* __restrict__ x,
                    float* __restrict__ out,
                    int Nn) {
    extern __shared__ char sm[];
    u16* Sa = (u16*)(sm + OFF_SA);
    u16* Sb = (u16*)(sm + OFF_SB);

    int tid  = threadIdx.x;
    int lane = tid & 31;
    int wrp  = tid >> 5;

    // reset counters for the NEXT invocation (off the critical path)
    {
        int gid = blockIdx.x * blockDim.x + tid;
        if (gid < Nn) g_cnt[gid] = 0;
        if (gid == 0) g_overcnt = 0;
    }

    int m0 = lane >> 2;                // fragment row (0..7)
    int cq = lane & 3;                 // k/n quad (0..3)
    int nt0 = wrp * 2;                 // this warp's two n-tiles

    // B fragment row bases in global WT ([n][k] layout, k-major)
    int n0 = (nt0 + 0) * 8 + m0;
    int n1 = (nt0 + 1) * 8 + m0;
    const u16* wa0 = g_WTa + n0 * F;
    const u16* wa1 = g_WTa + n1 * F;
    const u16* wb0 = g_WTb + n0 * F;
    const u16* wb1 = g_WTb + n1 * F;
    int kbase = cq * 2;

    // ldmatrix lane addressing: row = lane&15, col-block = (lane>>4)*8
    u32 lm_row = lane & 15;
    u32 lm_col = (lane >> 4) << 3;
    u32 addrSa = smem_u32(Sa) + (lm_row * SPAD + lm_col) * 2;
    u32 addrSb = smem_u32(Sb) + (lm_row * SPAD + lm_col) * 2;

    // staging assignment: thread -> (row r, 8-col segment seg)
    int sr  = tid >> 4;
    int seg = tid & 15;

    int ntiles = (Nn + 15) >> 4;
    for (int t = blockIdx.x; t < ntiles; t += gridDim.x) {
        int row0 = t << 4;

        // ---- stage 16 S rows: pure LDG.128 -> STS.128 copy (hi and lo)
        {
            int row = row0 + sr;
            size_t gidx = (size_t)row * F + seg * 8;
            uint4 hv = (row < Nn) ? *(const uint4*)&g_Shi[gidx]
                                  : make_uint4(0, 0, 0, 0);
            uint4 lv = (row < Nn) ? *(const uint4*)&g_Slo[gidx]
                                  : make_uint4(0, 0, 0, 0);
            *(uint4*)&Sa[sr * SPAD + seg * 8] = hv;
            *(uint4*)&Sb[sr * SPAD + seg * 8] = lv;
        }
        __syncthreads();

        // ---- mainloop: 8 k-steps x (ldmatrix A hi/lo + B from L1 + 6 mma)
        float acc0[4] = {0.f, 0.f, 0.f, 0.f};
        float acc1[4] = {0.f, 0.f, 0.f, 0.f};

        #pragma unroll
        for (int ks = 0; ks < 8; ks++) {
            int kk = ks * 16 + kbase;
            u32 ah0, ah1, ah2, ah3, al0, al1, al2, al3;
            LDMATRIX_X4(ah0, ah1, ah2, ah3, addrSa + ks * 32);
            LDMATRIX_X4(al0, al1, al2, al3, addrSb + ks * 32);

            u32 b00h = *(const u32*)&wa0[kk];
            u32 b01h = *(const u32*)&wa0[kk + 8];
            u32 b00l = *(const u32*)&wb0[kk];
            u32 b01l = *(const u32*)&wb0[kk + 8];
            u32 b10h = *(const u32*)&wa1[kk];
            u32 b11h = *(const u32*)&wa1[kk + 8];
            u32 b10l = *(const u32*)&wb1[kk];
            u32 b11l = *(const u32*)&wb1[kk + 8];

            MMA_BF16(acc0, ah0, ah1, ah2, ah3, b00h, b01h);
            MMA_BF16(acc0, al0, al1, al2, al3, b00h, b01h);
            MMA_BF16(acc0, ah0, ah1, ah2, ah3, b00l, b01l);

            MMA_BF16(acc1, ah0, ah1, ah2, ah3, b10h, b11h);
            MMA_BF16(acc1, al0, al1, al2, al3, b10h, b11h);
            MMA_BF16(acc1, ah0, ah1, ah2, ah3, b10l, b11l);
        }

        // ---- writeout: D + x residual
        int r0 = row0 + m0;
        int r1 = row0 + m0 + 8;
        #pragma unroll
        for (int j = 0; j < 2; j++) {
            float* ac = j ? acc1 : acc0;
            int col = (nt0 + j) * 8 + cq * 2;
            if (r0 < Nn) {
                float2 xv = *(const float2*)&x[(size_t)r0 * F + col];
                float2 o = make_float2(ac[0] + xv.x, ac[1] + xv.y);
                *(float2*)&out[(size_t)r0 * F + col] = o;
            }
            if (r1 < Nn) {
                float2 xv = *(const float2*)&x[(size_t)r1 * F + col];
                float2 o = make_float2(ac[2] + xv.x, ac[3] + xv.y);
                *(float2*)&out[(size_t)r1 * F + col] = o;
            }
        }
        __syncthreads();   // protect S staging before next tile
    }
}

// ---------------------------------------------------------------------------
extern "C" void kernel_launch(void* const* d_in, const int* in_sizes, int n_in,
                              void* d_out, int out_size) {
    const float* x      = (const float*)d_in[0];
    const float* h0     = (const float*)d_in[1];
    const float* ew     = (const float*)d_in[2];
    const float* weight = (const float*)d_in[3];
    const float* lamda  = (const float*)d_in[4];
    const float* alpha  = (const float*)d_in[5];
    const int*   esrc   = (const int*)d_in[6];
    const int*   edst   = (const int*)d_in[7];
    const int*   lp     = (const int*)d_in[8];

    int Nn = in_sizes[0] / F;
    int E  = in_sizes[2];
    float* out = (float*)d_out;

    // 1) bucket fill (1 edge/thread) + fused WT hi/lo build
    fill_kernel<<<(E + 255) / 256, 256>>>(ew, esrc, edst, E, weight, lamda, lp);

    // 2) gather + S fuse + bf16 split (one warp per row)
    long long gthreads = (long long)Nn * 32;
    gather_kernel<<<(int)((gthreads + 255) / 256), 256>>>(x, h0, alpha, Nn);

    // 3) HMMA epilogue, 3 blocks/SM (+ counter reset for next call)
    cudaFuncSetAttribute(mma_epilogue_kernel,
                         cudaFuncAttributeMaxDynamicSharedMemorySize, SMEM_EPI);
    mma_epilogue_kernel<<<592, 256, SMEM_EPI>>>(x, out, Nn);
}

// round 15
// speedup vs baseline: 1.4319x; 1.4319x over previous
#include <cuda_runtime.h>
#include <cuda_bf16.h>
#include <math.h>

#define F 128
#define NMAX 50000
#define EMAX 800000
#define CAP 64      // bucket capacity per destination row (P(deg>=64) ~ 1e-13)

typedef unsigned int       u32;
typedef unsigned short     u16;
typedef unsigned long long u64;

// static scratch (no allocations allowed; zero-initialized at load)
__device__ u16    g_Shi[(size_t)NMAX * F];         // bf16 hi of S
__device__ u16    g_Slo[(size_t)NMAX * F];         // bf16 residual of S
__device__ float2 g_slots[(size_t)NMAX * CAP];     // (src_bits, w) buckets
__device__ int    g_cnt[NMAX];                     // reset by epilogue for next call
__device__ float4 g_over[EMAX];                    // overflow edges
__device__ int    g_overcnt;

// ---------------------------------------------------------------------------
// Kernel 1: bucket fill. One thread per edge (proven throughput-bound config).
// ---------------------------------------------------------------------------
__global__ void fill_kernel(const float* __restrict__ edge_w,
                            const int* __restrict__ edge_src,
                            const int* __restrict__ edge_dst,
                            int E) {
    int e = blockIdx.x * blockDim.x + threadIdx.x;
    if (e >= E) return;
    int d = edge_dst[e];
    int s = edge_src[e];
    float w = edge_w[e];
    int pos = atomicAdd(&g_cnt[d], 1);
    if (pos < CAP) {
        g_slots[(size_t)d * CAP + pos] = make_float2(__int_as_float(s), w);
    } else {
        int o = atomicAdd(&g_overcnt, 1);
        if (o < EMAX)
            g_over[o] = make_float4(__int_as_float(s), __int_as_float(d), w, 0.f);
    }
}

// ---------------------------------------------------------------------------
// Kernel 2: gather + S fuse + bf16 hi/lo split. One warp per row (R12-proven).
// ---------------------------------------------------------------------------
__global__ void gather_kernel(const float* __restrict__ x,
                              const float* __restrict__ h0,
                              const float* __restrict__ alpha_p,
                              int Nn) {
    int gtid = blockIdx.x * blockDim.x + threadIdx.x;
    int row = gtid >> 5;
    int lane = gtid & 31;
    if (row >= Nn) return;

    float alpha = alpha_p[0];
    float oma = 1.0f - alpha;

    int cnt_raw = g_cnt[row];
    int cnt = min(cnt_raw, CAP);

    float4 acc = make_float4(0.f, 0.f, 0.f, 0.f);
    const float2* slotp = g_slots + (size_t)row * CAP;

    for (int base = 0; base < cnt; base += 32) {
        int m = min(32, cnt - base);
        float2 myslot = (lane < m) ? slotp[base + lane] : make_float2(0.f, 0.f);
        int ms = __float_as_int(myslot.x);
        #pragma unroll 4
        for (int e = 0; e < m; e++) {
            int   s  = __shfl_sync(0xffffffffu, ms, e);
            float wt = __shfl_sync(0xffffffffu, myslot.y, e);
            float4 v = ((const float4*)(x + (size_t)s * F))[lane];
            acc.x += wt * v.x;
            acc.y += wt * v.y;
            acc.z += wt * v.z;
            acc.w += wt * v.w;
        }
    }

    if (cnt_raw > CAP) {                       // statistically never
        int oc = g_overcnt;
        if (oc > EMAX) oc = EMAX;
        for (int o = 0; o < oc; o++) {
            float4 ov = g_over[o];
            if (__float_as_int(ov.y) == row) {
                int s = __float_as_int(ov.x);
                float wt = ov.z;
                float4 v = ((const float4*)(x + (size_t)s * F))[lane];
                acc.x += wt * v.x;
                acc.y += wt * v.y;
                acc.z += wt * v.z;
                acc.w += wt * v.w;
            }
        }
    }

    float4 hv = ((const float4*)(h0 + (size_t)row * F))[lane];
    float Sx = oma * acc.x + alpha * hv.x;
    float Sy = oma * acc.y + alpha * hv.y;
    float Sz = oma * acc.z + alpha * hv.z;
    float Sw = oma * acc.w + alpha * hv.w;

    __nv_bfloat162 h01 = __floats2bfloat162_rn(Sx, Sy);
    __nv_bfloat162 h23 = __floats2bfloat162_rn(Sz, Sw);
    __nv_bfloat162 l01 = __floats2bfloat162_rn(
        Sx - __bfloat162float(h01.x), Sy - __bfloat162float(h01.y));
    __nv_bfloat162 l23 = __floats2bfloat162_rn(
        Sz - __bfloat162float(h23.x), Sw - __bfloat162float(h23.y));
    u64 hvv = (u64)(*(u32*)&h01) | ((u64)(*(u32*)&h23) << 32);
    u64 lvv = (u64)(*(u32*)&l01) | ((u64)(*(u32*)&l23) << 32);
    *(u64*)&g_Shi[(size_t)row * F + 4 * lane] = hvv;
    *(u64*)&g_Slo[(size_t)row * F + 4 * lane] = lvv;
}

// ---------------------------------------------------------------------------
// Kernel 3: HMMA epilogue (R12 design, MT=32 tiles).
//   out = S @ W' + x; D = Sa@Wa + Sb@Wa + Sa@Wb (fp32 accum).
// R15 delta vs R12: 32-row tiles -> half the barriers/staging exposures,
// 2x LDG batch in staging, 96 MMAs per warp between barriers. B fragments
// stay register-hoisted (proven). Each warp: 2 row-blocks x 2 n-tiles.
// ---------------------------------------------------------------------------
#define SPAD 136                        // u16 row stride (272 bytes)
#define MT   32
#define OFF_WTA 0
#define OFF_WTB (128 * SPAD * 2)        // 34816
#define OFF_SA  (2 * 128 * SPAD * 2)    // 69632
#define OFF_SB  (OFF_SA + MT * SPAD * 2)
#define SMEM_EPI (OFF_SB + MT * SPAD * 2)   // 87040 bytes

#define MMA_BF16(c, a0, a1, a2, a3, b0, b1) \
    asm volatile("mma.sync.aligned.m16n8k16.row.col.f32.bf16.bf16.f32 " \
        "{%0,%1,%2,%3}, {%4,%5,%6,%7}, {%8,%9}, {%0,%1,%2,%3};" \
        : "+f"((c)[0]), "+f"((c)[1]), "+f"((c)[2]), "+f"((c)[3]) \
        : "r"(a0), "r"(a1), "r"(a2), "r"(a3), "r"(b0), "r"(b1))

#define LDMATRIX_X4(r0, r1, r2, r3, addr) \
    asm volatile("ldmatrix.sync.aligned.m8n8.x4.shared.b16 {%0,%1,%2,%3}, [%4];" \
        : "=r"(r0), "=r"(r1), "=r"(r2), "=r"(r3) : "r"(addr))

__device__ __forceinline__ u32 smem_u32(const void* p) {
    u32 a;
    asm("{ .reg .u64 t; cvta.to.shared.u64 t, %1; cvt.u32.u64 %0, t; }"
        : "=r"(a) : "l"(p));
    return a;
}

__global__ void __launch_bounds__(256, 2)
mma_epilogue_kernel(const float* __restrict__ x,
                    const float* __restrict__ weight,
                    const float* __restrict__ lamda_p,
                    const int* __restrict__ l_p,
                    float* __restrict__ out,
                    int Nn) {
    extern __shared__ char sm[];
    u16* WTa = (u16*)(sm + OFF_WTA);
    u16* WTb = (u16*)(sm + OFF_WTB);
    u16* Sa  = (u16*)(sm + OFF_SA);
    u16* Sb  = (u16*)(sm + OFF_SB);

    int tid  = threadIdx.x;
    int lane = tid & 31;
    int wrp  = tid >> 5;

    // reset counters for the NEXT invocation (off the critical path)
    {
        int gid = blockIdx.x * blockDim.x + tid;
        if (gid < Nn) g_cnt[gid] = 0;
        if (gid == 0) g_overcnt = 0;
    }

    float theta = logf(lamda_p[0] / (float)l_p[0] + 1.0f);
    float omt = 1.0f - theta;

    // Build WT hi/lo: WT[n][k] = W'[k][n] = theta*W[k][n] + (k==n)*(1-theta)
    for (int i = tid; i < F * F; i += 256) {
        int k = i >> 7;
        int n = i & 127;
        float v = theta * weight[i];
        if (k == n) v += omt;
        __nv_bfloat16 h = __float2bfloat16(v);
        float res = v - __bfloat162float(h);
        __nv_bfloat16 l = __float2bfloat16(res);
        WTa[n * SPAD + k] = *(u16*)&h;
        WTb[n * SPAD + k] = *(u16*)&l;
    }
    __syncthreads();

    int m0 = lane >> 2;                // fragment row (0..7)
    int cq = lane & 3;                 // k/n quad (0..3)
    int nt0 = wrp * 2;                 // this warp's two n-tiles

    // ---- hoist B fragments (W' constant across all tiles): 64 u32 regs
    u32 Bf[2][8][4];
    #pragma unroll
    for (int j = 0; j < 2; j++) {
        int n = (nt0 + j) * 8 + m0;
        #pragma unroll
        for (int ks = 0; ks < 8; ks++) {
            int kk = ks * 16 + cq * 2;
            Bf[j][ks][0] = *(u32*)&WTa[n * SPAD + kk];
            Bf[j][ks][1] = *(u32*)&WTa[n * SPAD + kk + 8];
            Bf[j][ks][2] = *(u32*)&WTb[n * SPAD + kk];
            Bf[j][ks][3] = *(u32*)&WTb[n * SPAD + kk + 8];
        }
    }

    // ldmatrix lane addressing: row = lane&15, col-block = (lane>>4)*8
    u32 lm_row = lane & 15;
    u32 lm_col = (lane >> 4) << 3;
    u32 addrSa = smem_u32(Sa) + (lm_row * SPAD + lm_col) * 2;
    u32 addrSb = smem_u32(Sb) + (lm_row * SPAD + lm_col) * 2;

    // staging assignment: thread -> (rows sr, sr+16; 8-col segment seg)
    int sr  = tid >> 4;
    int seg = tid & 15;

    int ntiles = (Nn + MT - 1) / MT;
    for (int t = blockIdx.x; t < ntiles; t += gridDim.x) {
        int row0 = t * MT;

        // ---- stage 32 S rows: pure LDG.128 -> STS.128 (hi and lo), 2 rows/thr
        #pragma unroll
        for (int h = 0; h < 2; h++) {
            int r = sr + h * 16;
            int row = row0 + r;
            size_t gidx = (size_t)row * F + seg * 8;
            uint4 hv = (row < Nn) ? *(const uint4*)&g_Shi[gidx]
                                  : make_uint4(0, 0, 0, 0);
            uint4 lv = (row < Nn) ? *(const uint4*)&g_Slo[gidx]
                                  : make_uint4(0, 0, 0, 0);
            *(uint4*)&Sa[r * SPAD + seg * 8] = hv;
            *(uint4*)&Sb[r * SPAD + seg * 8] = lv;
        }
        __syncthreads();

        // ---- mainloop: 2 row-blocks x 8 k-steps x (2 ldmatrix + 6 mma)
        float acc[2][2][4];
        #pragma unroll
        for (int rb = 0; rb < 2; rb++)
            #pragma unroll
            for (int j = 0; j < 2; j++)
                #pragma unroll
                for (int c = 0; c < 4; c++) acc[rb][j][c] = 0.f;

        #pragma unroll
        for (int rb = 0; rb < 2; rb++) {
            u32 baseA = addrSa + rb * (16 * SPAD * 2);
            u32 baseB = addrSb + rb * (16 * SPAD * 2);
            #pragma unroll
            for (int ks = 0; ks < 8; ks++) {
                u32 ah0, ah1, ah2, ah3, al0, al1, al2, al3;
                LDMATRIX_X4(ah0, ah1, ah2, ah3, baseA + ks * 32);
                LDMATRIX_X4(al0, al1, al2, al3, baseB + ks * 32);

                MMA_BF16(acc[rb][0], ah0, ah1, ah2, ah3, Bf[0][ks][0], Bf[0][ks][1]);
                MMA_BF16(acc[rb][0], al0, al1, al2, al3, Bf[0][ks][0], Bf[0][ks][1]);
                MMA_BF16(acc[rb][0], ah0, ah1, ah2, ah3, Bf[0][ks][2], Bf[0][ks][3]);

                MMA_BF16(acc[rb][1], ah0, ah1, ah2, ah3, Bf[1][ks][0], Bf[1][ks][1]);
                MMA_BF16(acc[rb][1], al0, al1, al2, al3, Bf[1][ks][0], Bf[1][ks][1]);
                MMA_BF16(acc[rb][1], ah0, ah1, ah2, ah3, Bf[1][ks][2], Bf[1][ks][3]);
            }
        }

        // ---- writeout: D + x residual
        #pragma unroll
        for (int rb = 0; rb < 2; rb++) {
            int r0 = row0 + rb * 16 + m0;
            int r1 = r0 + 8;
            #pragma unroll
            for (int j = 0; j < 2; j++) {
                float* ac = acc[rb][j];
                int col = (nt0 + j) * 8 + cq * 2;
                if (r0 < Nn) {
                    float2 xv = *(const float2*)&x[(size_t)r0 * F + col];
                    float2 o = make_float2(ac[0] + xv.x, ac[1] + xv.y);
                    *(float2*)&out[(size_t)r0 * F + col] = o;
                }
                if (r1 < Nn) {
                    float2 xv = *(const float2*)&x[(size_t)r1 * F + col];
                    float2 o = make_float2(ac[2] + xv.x, ac[3] + xv.y);
                    *(float2*)&out[(size_t)r1 * F + col] = o;
                }
            }
        }
        __syncthreads();   // protect S staging before next tile
    }
}

// ---------------------------------------------------------------------------
extern "C" void kernel_launch(void* const* d_in, const int* in_sizes, int n_in,
                              void* d_out, int out_size) {
    const float* x      = (const float*)d_in[0];
    const float* h0     = (const float*)d_in[1];
    const float* ew     = (const float*)d_in[2];
    const float* weight = (const float*)d_in[3];
    const float* lamda  = (const float*)d_in[4];
    const float* alpha  = (const float*)d_in[5];
    const int*   esrc   = (const int*)d_in[6];
    const int*   edst   = (const int*)d_in[7];
    const int*   lp     = (const int*)d_in[8];

    int Nn = in_sizes[0] / F;
    int E  = in_sizes[2];
    float* out = (float*)d_out;

    // 1) bucket fill (1 edge/thread)
    fill_kernel<<<(E + 255) / 256, 256>>>(ew, esrc, edst, E);

    // 2) gather + S fuse + bf16 split (one warp per row)
    long long gthreads = (long long)Nn * 32;
    gather_kernel<<<(int)((gthreads + 255) / 256), 256>>>(x, h0, alpha, Nn);

    // 3) HMMA epilogue, 32-row tiles (+ counter reset for next call)
    cudaFuncSetAttribute(mma_epilogue_kernel,
                         cudaFuncAttributeMaxDynamicSharedMemorySize, SMEM_EPI);
    mma_epilogue_kernel<<<296, 256, SMEM_EPI>>>(x, weight, lamda, lp, out, Nn);
}

// round 16
// speedup vs baseline: 1.4567x; 1.0174x over previous
#include <cuda_runtime.h>
#include <cuda_bf16.h>
#include <math.h>

#define F 128
#define NMAX 50000
#define EMAX 800000
#define CAP 64      // bucket capacity per destination row (P(deg>=64) ~ 1e-13)

typedef unsigned int       u32;
typedef unsigned short     u16;
typedef unsigned long long u64;

// static scratch (no allocations allowed; zero-initialized at load)
__device__ u16    g_Shi[(size_t)NMAX * F];         // bf16 hi of S
__device__ u16    g_Slo[(size_t)NMAX * F];         // bf16 residual of S
__device__ float2 g_slots[(size_t)NMAX * CAP];     // (src_bits, w) buckets
__device__ int    g_cnt[NMAX];                     // reset by epilogue for next call
__device__ float4 g_over[EMAX];                    // overflow edges
__device__ int    g_overcnt;

// ---------------------------------------------------------------------------
// Kernel 1: bucket fill. One thread per edge (proven throughput-bound config).
// ---------------------------------------------------------------------------
__global__ void fill_kernel(const float* __restrict__ edge_w,
                            const int* __restrict__ edge_src,
                            const int* __restrict__ edge_dst,
                            int E) {
    int e = blockIdx.x * blockDim.x + threadIdx.x;
    if (e >= E) return;
    int d = edge_dst[e];
    int s = edge_src[e];
    float w = edge_w[e];
    int pos = atomicAdd(&g_cnt[d], 1);
    if (pos < CAP) {
        g_slots[(size_t)d * CAP + pos] = make_float2(__int_as_float(s), w);
    } else {
        int o = atomicAdd(&g_overcnt, 1);
        if (o < EMAX)
            g_over[o] = make_float4(__int_as_float(s), __int_as_float(d), w, 0.f);
    }
}

// ---------------------------------------------------------------------------
// Kernel 2: gather + S fuse + bf16 hi/lo split. One warp per row (R12-proven).
// ---------------------------------------------------------------------------
__global__ void gather_kernel(const float* __restrict__ x,
                              const float* __restrict__ h0,
                              const float* __restrict__ alpha_p,
                              int Nn) {
    int gtid = blockIdx.x * blockDim.x + threadIdx.x;
    int row = gtid >> 5;
    int lane = gtid & 31;
    if (row >= Nn) return;

    float alpha = alpha_p[0];
    float oma = 1.0f - alpha;

    int cnt_raw = g_cnt[row];
    int cnt = min(cnt_raw, CAP);

    float4 acc = make_float4(0.f, 0.f, 0.f, 0.f);
    const float2* slotp = g_slots + (size_t)row * CAP;

    for (int base = 0; base < cnt; base += 32) {
        int m = min(32, cnt - base);
        float2 myslot = (lane < m) ? slotp[base + lane] : make_float2(0.f, 0.f);
        int ms = __float_as_int(myslot.x);
        #pragma unroll 4
        for (int e = 0; e < m; e++) {
            int   s  = __shfl_sync(0xffffffffu, ms, e);
            float wt = __shfl_sync(0xffffffffu, myslot.y, e);
            float4 v = ((const float4*)(x + (size_t)s * F))[lane];
            acc.x += wt * v.x;
            acc.y += wt * v.y;
            acc.z += wt * v.z;
            acc.w += wt * v.w;
        }
    }

    if (cnt_raw > CAP) {                       // statistically never
        int oc = g_overcnt;
        if (oc > EMAX) oc = EMAX;
        for (int o = 0; o < oc; o++) {
            float4 ov = g_over[o];
            if (__float_as_int(ov.y) == row) {
                int s = __float_as_int(ov.x);
                float wt = ov.z;
                float4 v = ((const float4*)(x + (size_t)s * F))[lane];
                acc.x += wt * v.x;
                acc.y += wt * v.y;
                acc.z += wt * v.z;
                acc.w += wt * v.w;
            }
        }
    }

    float4 hv = ((const float4*)(h0 + (size_t)row * F))[lane];
    float Sx = oma * acc.x + alpha * hv.x;
    float Sy = oma * acc.y + alpha * hv.y;
    float Sz = oma * acc.z + alpha * hv.z;
    float Sw = oma * acc.w + alpha * hv.w;

    __nv_bfloat162 h01 = __floats2bfloat162_rn(Sx, Sy);
    __nv_bfloat162 h23 = __floats2bfloat162_rn(Sz, Sw);
    __nv_bfloat162 l01 = __floats2bfloat162_rn(
        Sx - __bfloat162float(h01.x), Sy - __bfloat162float(h01.y));
    __nv_bfloat162 l23 = __floats2bfloat162_rn(
        Sz - __bfloat162float(h23.x), Sw - __bfloat162float(h23.y));
    u64 hvv = (u64)(*(u32*)&h01) | ((u64)(*(u32*)&h23) << 32);
    u64 lvv = (u64)(*(u32*)&l01) | ((u64)(*(u32*)&l23) << 32);
    *(u64*)&g_Shi[(size_t)row * F + 4 * lane] = hvv;
    *(u64*)&g_Slo[(size_t)row * F + 4 * lane] = lvv;
}

// ---------------------------------------------------------------------------
// Kernel 3: HMMA epilogue, DOUBLE-BUFFERED staging + x residual prefetch.
//   out = S @ W' + x; D = Sa@Wa + Sb@Wa + Sa@Wb (fp32 accum).
// Per tile: [prefetch next-S LDG + current-x LDG] || mainloop(buf p),
// then STS->buf 1-p, writeout (x already in regs), ONE syncthreads.
// Serial chain loses the cold writeout x-LDG and the staging LDG+STS+bar.
// ---------------------------------------------------------------------------
#define SPAD 136                        // u16 row stride (272 bytes)
#define OFF_WTA 0
#define OFF_WTB (128 * SPAD * 2)        // 34816
#define OFF_S   (2 * 128 * SPAD * 2)    // 69632
#define BUFSZ   (16 * SPAD * 2)         // 4352 bytes per Sa/Sb buffer
#define SMEM_EPI (OFF_S + 4 * BUFSZ)    // 87040 bytes

#define MMA_BF16(c, a0, a1, a2, a3, b0, b1) \
    asm volatile("mma.sync.aligned.m16n8k16.row.col.f32.bf16.bf16.f32 " \
        "{%0,%1,%2,%3}, {%4,%5,%6,%7}, {%8,%9}, {%0,%1,%2,%3};" \
        : "+f"((c)[0]), "+f"((c)[1]), "+f"((c)[2]), "+f"((c)[3]) \
        : "r"(a0), "r"(a1), "r"(a2), "r"(a3), "r"(b0), "r"(b1))

#define LDMATRIX_X4(r0, r1, r2, r3, addr) \
    asm volatile("ldmatrix.sync.aligned.m8n8.x4.shared.b16 {%0,%1,%2,%3}, [%4];" \
        : "=r"(r0), "=r"(r1), "=r"(r2), "=r"(r3) : "r"(addr))

__device__ __forceinline__ u32 smem_u32(const void* p) {
    u32 a;
    asm("{ .reg .u64 t; cvta.to.shared.u64 t, %1; cvt.u32.u64 %0, t; }"
        : "=r"(a) : "l"(p));
    return a;
}

__global__ void __launch_bounds__(256, 2)
mma_epilogue_kernel(const float* __restrict__ x,
                    const float* __restrict__ weight,
                    const float* __restrict__ lamda_p,
                    const int* __restrict__ l_p,
                    float* __restrict__ out,
                    int Nn) {
    extern __shared__ char sm[];
    u16* WTa = (u16*)(sm + OFF_WTA);
    u16* WTb = (u16*)(sm + OFF_WTB);
    // buffers: [Sa0][Sb0][Sa1][Sb1]
    u16* Sa0 = (u16*)(sm + OFF_S);
    u16* Sb0 = (u16*)(sm + OFF_S + BUFSZ);
    u16* Sa1 = (u16*)(sm + OFF_S + 2 * BUFSZ);
    u16* Sb1 = (u16*)(sm + OFF_S + 3 * BUFSZ);

    int tid  = threadIdx.x;
    int lane = tid & 31;
    int wrp  = tid >> 5;

    // reset counters for the NEXT invocation (off the critical path)
    {
        int gid = blockIdx.x * blockDim.x + tid;
        if (gid < Nn) g_cnt[gid] = 0;
        if (gid == 0) g_overcnt = 0;
    }

    float theta = logf(lamda_p[0] / (float)l_p[0] + 1.0f);
    float omt = 1.0f - theta;

    // Build WT hi/lo: WT[n][k] = W'[k][n] = theta*W[k][n] + (k==n)*(1-theta)
    for (int i = tid; i < F * F; i += 256) {
        int k = i >> 7;
        int n = i & 127;
        float v = theta * weight[i];
        if (k == n) v += omt;
        __nv_bfloat16 h = __float2bfloat16(v);
        float res = v - __bfloat162float(h);
        __nv_bfloat16 l = __float2bfloat16(res);
        WTa[n * SPAD + k] = *(u16*)&h;
        WTb[n * SPAD + k] = *(u16*)&l;
    }
    __syncthreads();

    int m0 = lane >> 2;                // fragment row (0..7)
    int cq = lane & 3;                 // k/n quad (0..3)
    int nt0 = wrp * 2;                 // this warp's two n-tiles

    // ---- hoist B fragments (W' constant across all tiles): 64 u32 regs
    u32 Bf[2][8][4];
    #pragma unroll
    for (int j = 0; j < 2; j++) {
        int n = (nt0 + j) * 8 + m0;
        #pragma unroll
        for (int ks = 0; ks < 8; ks++) {
            int kk = ks * 16 + cq * 2;
            Bf[j][ks][0] = *(u32*)&WTa[n * SPAD + kk];
            Bf[j][ks][1] = *(u32*)&WTa[n * SPAD + kk + 8];
            Bf[j][ks][2] = *(u32*)&WTb[n * SPAD + kk];
            Bf[j][ks][3] = *(u32*)&WTb[n * SPAD + kk + 8];
        }
    }

    // ldmatrix lane addressing: row = lane&15, col-block = (lane>>4)*8
    u32 lmoff = ((lane & 15) * SPAD + ((lane >> 4) << 3)) * 2;
    u32 aSa0 = smem_u32(Sa0) + lmoff;
    u32 aSb0 = smem_u32(Sb0) + lmoff;
    u32 aSa1 = smem_u32(Sa1) + lmoff;
    u32 aSb1 = smem_u32(Sb1) + lmoff;

    // staging assignment: thread -> (row sr, 8-col segment seg)
    int sr  = tid >> 4;
    int seg = tid & 15;

    int ntiles = (Nn + 15) >> 4;

    // ---- prologue: stage first tile into buffer 0
    {
        int row = (blockIdx.x << 4) + sr;
        uint4 hv = make_uint4(0, 0, 0, 0), lv = make_uint4(0, 0, 0, 0);
        if (blockIdx.x < ntiles && row < Nn) {
            size_t gidx = (size_t)row * F + seg * 8;
            hv = *(const uint4*)&g_Shi[gidx];
            lv = *(const uint4*)&g_Slo[gidx];
        }
        *(uint4*)&Sa0[sr * SPAD + seg * 8] = hv;
        *(uint4*)&Sb0[sr * SPAD + seg * 8] = lv;
    }
    __syncthreads();

    int p = 0;
    for (int t = blockIdx.x; t < ntiles; t += gridDim.x) {
        int row0 = t << 4;

        // ---- prefetch next tile's S into regs (independent of mainloop)
        uint4 hvN = make_uint4(0, 0, 0, 0), lvN = make_uint4(0, 0, 0, 0);
        {
            int tn = t + gridDim.x;
            int row = (tn << 4) + sr;
            if (tn < ntiles && row < Nn) {
                size_t gidx = (size_t)row * F + seg * 8;
                hvN = *(const uint4*)&g_Shi[gidx];
                lvN = *(const uint4*)&g_Slo[gidx];
            }
        }

        // ---- prefetch current tile's x residuals (consumed at writeout)
        int r0 = row0 + m0;
        int r1 = r0 + 8;
        float2 xv[2][2];
        #pragma unroll
        for (int j = 0; j < 2; j++) {
            int col = (nt0 + j) * 8 + cq * 2;
            xv[j][0] = (r0 < Nn) ? *(const float2*)&x[(size_t)r0 * F + col]
                                 : make_float2(0.f, 0.f);
            xv[j][1] = (r1 < Nn) ? *(const float2*)&x[(size_t)r1 * F + col]
                                 : make_float2(0.f, 0.f);
        }

        // ---- mainloop from buffer p (LDGs above fly during this)
        u32 baseA = p ? aSa1 : aSa0;
        u32 baseB = p ? aSb1 : aSb0;

        float acc0[4] = {0.f, 0.f, 0.f, 0.f};
        float acc1[4] = {0.f, 0.f, 0.f, 0.f};

        #pragma unroll
        for (int ks = 0; ks < 8; ks++) {
            u32 ah0, ah1, ah2, ah3, al0, al1, al2, al3;
            LDMATRIX_X4(ah0, ah1, ah2, ah3, baseA + ks * 32);
            LDMATRIX_X4(al0, al1, al2, al3, baseB + ks * 32);

            MMA_BF16(acc0, ah0, ah1, ah2, ah3, Bf[0][ks][0], Bf[0][ks][1]);
            MMA_BF16(acc0, al0, al1, al2, al3, Bf[0][ks][0], Bf[0][ks][1]);
            MMA_BF16(acc0, ah0, ah1, ah2, ah3, Bf[0][ks][2], Bf[0][ks][3]);

            MMA_BF16(acc1, ah0, ah1, ah2, ah3, Bf[1][ks][0], Bf[1][ks][1]);
            MMA_BF16(acc1, al0, al1, al2, al3, Bf[1][ks][0], Bf[1][ks][1]);
            MMA_BF16(acc1, ah0, ah1, ah2, ah3, Bf[1][ks][2], Bf[1][ks][3]);
        }

        // ---- stage next tile into buffer 1-p (no barrier needed before:
        // this buffer was fully consumed in the PREVIOUS iteration, and the
        // iteration-ending bar below orders it for the next mainloop)
        {
            u16* SaN = p ? Sa0 : Sa1;
            u16* SbN = p ? Sb0 : Sb1;
            *(uint4*)&SaN[sr * SPAD + seg * 8] = hvN;
            *(uint4*)&SbN[sr * SPAD + seg * 8] = lvN;
        }

        // ---- writeout: D + prefetched x residual
        #pragma unroll
        for (int j = 0; j < 2; j++) {
            float* ac = j ? acc1 : acc0;
            int col = (nt0 + j) * 8 + cq * 2;
            if (r0 < Nn) {
                float2 o = make_float2(ac[0] + xv[j][0].x, ac[1] + xv[j][0].y);
                *(float2*)&out[(size_t)r0 * F + col] = o;
            }
            if (r1 < Nn) {
                float2 o = make_float2(ac[2] + xv[j][1].x, ac[3] + xv[j][1].y);
                *(float2*)&out[(size_t)r1 * F + col] = o;
            }
        }

        __syncthreads();   // next-buffer writes visible; current buffer free
        p ^= 1;
    }
}

// ---------------------------------------------------------------------------
extern "C" void kernel_launch(void* const* d_in, const int* in_sizes, int n_in,
                              void* d_out, int out_size) {
    const float* x      = (const float*)d_in[0];
    const float* h0     = (const float*)d_in[1];
    const float* ew     = (const float*)d_in[2];
    const float* weight = (const float*)d_in[3];
    const float* lamda  = (const float*)d_in[4];
    const float* alpha  = (const float*)d_in[5];
    const int*   esrc   = (const int*)d_in[6];
    const int*   edst   = (const int*)d_in[7];
    const int*   lp     = (const int*)d_in[8];

    int Nn = in_sizes[0] / F;
    int E  = in_sizes[2];
    float* out = (float*)d_out;

    // 1) bucket fill (1 edge/thread)
    fill_kernel<<<(E + 255) / 256, 256>>>(ew, esrc, edst, E);

    // 2) gather + S fuse + bf16 split (one warp per row)
    long long gthreads = (long long)Nn * 32;
    gather_kernel<<<(int)((gthreads + 255) / 256), 256>>>(x, h0, alpha, Nn);

    // 3) HMMA epilogue, double-buffered (+ counter reset for next call)
    cudaFuncSetAttribute(mma_epilogue_kernel,
                         cudaFuncAttributeMaxDynamicSharedMemorySize, SMEM_EPI);
    mma_epilogue_kernel<<<296, 256, SMEM_EPI>>>(x, weight, lamda, lp, out, Nn);
}